// round 16
// baseline (speedup 1.0000x reference)
#include <cuda_runtime.h>
#include <cuda_bf16.h>
#include <mma.h>
#include <cstdint>

using namespace nvcuda;

#define B_    8
#define C_    256
#define HW_   4096
#define W_    64
#define OC3   768
#define GRP   96
#define HEADS 64

// ------------------------- scratch (static device memory) -------------------
__device__ float g_qkv[(size_t)B_ * OC3 * HW_];
__device__ float g_agg[(size_t)B_ * OC3 * HW_];
__device__ float g_kv [(size_t)B_ * HEADS * 72];
// pre-converted bf16 hi/lo weights
__device__ __nv_bfloat16 g_wqhi[OC3 * C_];
__device__ __nv_bfloat16 g_wqlo[OC3 * C_];
__device__ __nv_bfloat16 g_wphi[C_ * 512];
__device__ __nv_bfloat16 g_wplo[C_ * 512];

__device__ __forceinline__ const float* ms_ch(int b, int c) {
    return (c < OC3) ? (g_qkv + ((size_t)(b * OC3 + c)) * HW_)
                     : (g_agg + ((size_t)(b * OC3 + (c - OC3))) * HW_);
}

__device__ __forceinline__ void bsplit2(float x, float y,
                                        __nv_bfloat162& hi, __nv_bfloat162& lo)
{
    __nv_bfloat16 hx = __float2bfloat16(x);
    __nv_bfloat16 hy = __float2bfloat16(y);
    __nv_bfloat16 lx = __float2bfloat16(x - __bfloat162float(hx));
    __nv_bfloat16 ly = __float2bfloat16(y - __bfloat162float(hy));
    hi = __halves2bfloat162(hx, hy);
    lo = __halves2bfloat162(lx, ly);
}
__device__ __forceinline__ void bsplit1(float x, __nv_bfloat16& hi, __nv_bfloat16& lo)
{
    hi = __float2bfloat16(x);
    lo = __float2bfloat16(x - __bfloat162float(hi));
}

// ------------------ f32 -> bf16 hi/lo pre-conversion (weights) --------------
__global__ __launch_bounds__(256) void cvt_kernel(
    const float* __restrict__ src, __nv_bfloat16* __restrict__ dhi,
    __nv_bfloat16* __restrict__ dlo, int n4)
{
    int i = blockIdx.x * 256 + threadIdx.x;
    if (i < n4) {
        float4 v = ((const float4*)src)[i];
        __nv_bfloat162 h0, l0, h1, l1;
        bsplit2(v.x, v.y, h0, l0);
        bsplit2(v.z, v.w, h1, l1);
        ((__nv_bfloat162*)dhi)[i * 2]     = h0;
        ((__nv_bfloat162*)dhi)[i * 2 + 1] = h1;
        ((__nv_bfloat162*)dlo)[i * 2]     = l0;
        ((__nv_bfloat162*)dlo)[i * 2 + 1] = l1;
    }
}

// ------------------- qkv GEMM via wmma bf16-split ---------------------------
// A (weights) staged by uint4 copies of pre-converted bf16; B (x) converted
// in-kernel as before.
__global__ __launch_bounds__(256, 2) void qkv_wmma_kernel(
    const float* __restrict__ Bm, float* __restrict__ Cm)
{
    constexpr int KDIM = 256;
    __shared__ __nv_bfloat16 sAhi[128][24];
    __shared__ __nv_bfloat16 sAlo[128][24];
    __shared__ __nv_bfloat16 sBhi[16][136];
    __shared__ __nv_bfloat16 sBlo[16][136];

    const int m0 = blockIdx.y * 128;
    const int n0 = blockIdx.x * 128;
    const int b  = n0 >> 12;
    const int p0 = n0 & 4095;
    const int tid = threadIdx.x;
    const int wid = tid >> 5;
    const int wy = wid >> 1;
    const int wx = wid & 1;

    wmma::fragment<wmma::accumulator, 16, 16, 16, float> acc[2][4];
    #pragma unroll
    for (int mi = 0; mi < 2; mi++)
        #pragma unroll
        for (int pi = 0; pi < 4; pi++)
            wmma::fill_fragment(acc[mi][pi], 0.0f);

    const float* Bbase = Bm + (size_t)b * KDIM * HW_ + p0;
    const int arow  = tid >> 1;
    const int ahalf = (tid & 1) * 8;
    const __nv_bfloat16* wqhiB = g_wqhi + (size_t)(m0 + arow) * KDIM + ahalf;
    const __nv_bfloat16* wqloB = g_wqlo + (size_t)(m0 + arow) * KDIM + ahalf;

    for (int k0 = 0; k0 < KDIM; k0 += 16) {
        // A slab: pure uint4 copies of pre-converted weights
        *(uint4*)&sAhi[arow][ahalf] = *(const uint4*)(wqhiB + k0);
        *(uint4*)&sAlo[arow][ahalf] = *(const uint4*)(wqloB + k0);
        // B slab: x converted in-kernel
        #pragma unroll
        for (int it = 0; it < 2; it++) {
            int lin = tid + it * 256;
            int kr = lin >> 5;
            int pq = (lin & 31) * 4;
            float4 v = *(const float4*)(Bbase + (size_t)(k0 + kr) * HW_ + pq);
            __nv_bfloat162 h0, l0, h1, l1;
            bsplit2(v.x, v.y, h0, l0);
            bsplit2(v.z, v.w, h1, l1);
            *(__nv_bfloat162*)&sBhi[kr][pq]     = h0;
            *(__nv_bfloat162*)&sBhi[kr][pq + 2] = h1;
            *(__nv_bfloat162*)&sBlo[kr][pq]     = l0;
            *(__nv_bfloat162*)&sBlo[kr][pq + 2] = l1;
        }
        __syncthreads();

        wmma::fragment<wmma::matrix_a, 16, 16, 16, __nv_bfloat16, wmma::row_major> ahi[2], alo[2];
        #pragma unroll
        for (int mi = 0; mi < 2; mi++) {
            wmma::load_matrix_sync(ahi[mi], &sAhi[wy * 32 + mi * 16][0], 24);
            wmma::load_matrix_sync(alo[mi], &sAlo[wy * 32 + mi * 16][0], 24);
        }
        #pragma unroll
        for (int pi = 0; pi < 4; pi++) {
            wmma::fragment<wmma::matrix_b, 16, 16, 16, __nv_bfloat16, wmma::row_major> bhi, blo;
            wmma::load_matrix_sync(bhi, &sBhi[0][wx * 64 + pi * 16], 136);
            wmma::load_matrix_sync(blo, &sBlo[0][wx * 64 + pi * 16], 136);
            #pragma unroll
            for (int mi = 0; mi < 2; mi++) {
                wmma::mma_sync(acc[mi][pi], ahi[mi], bhi, acc[mi][pi]);
                wmma::mma_sync(acc[mi][pi], ahi[mi], blo, acc[mi][pi]);
                wmma::mma_sync(acc[mi][pi], alo[mi], bhi, acc[mi][pi]);
            }
        }
        __syncthreads();
    }

    const size_t cb = (size_t)b * OC3 * HW_;
    #pragma unroll
    for (int mi = 0; mi < 2; mi++)
        #pragma unroll
        for (int pi = 0; pi < 4; pi++) {
            float* cp = Cm + cb + (size_t)(m0 + wy * 32 + mi * 16) * HW_
                        + p0 + wx * 64 + pi * 16;
            wmma::store_matrix_sync(cp, acc[mi][pi], HW_, wmma::mem_row_major);
        }
}

// ---------- proj GEMM via wmma bf16-split, att fused, BN + residual ---------
// A (w_proj) staged by uint4 copies of pre-converted bf16; att B in-kernel.
__global__ __launch_bounds__(256, 2) void proj_wmma_kernel(
    float* __restrict__ Cm, const float* __restrict__ xres,
    const float* __restrict__ gamma, const float* __restrict__ beta,
    const float* __restrict__ mean, const float* __restrict__ var)
{
    constexpr int KDIM = 512;
    __shared__ __nv_bfloat16 sAhi[128][24];
    __shared__ __nv_bfloat16 sAlo[128][24];
    __shared__ __nv_bfloat16 sBhi[16][136];
    __shared__ __nv_bfloat16 sBlo[16][136];
    __shared__ float kvs[HEADS * 72];
    __shared__ float s_inv[128];
    __shared__ float s_bias[128];
    __shared__ float stage[8][256];

    const int m0 = blockIdx.y * 128;
    const int n0 = blockIdx.x * 128;
    const int b  = n0 >> 12;
    const int p0 = n0 & 4095;
    const int tid = threadIdx.x;
    const int wid = tid >> 5;
    const int lane = tid & 31;
    const int wy = wid >> 1;
    const int wx = wid & 1;

    if (tid < 128) {
        int c = m0 + tid;
        float iv = gamma[c] * rsqrtf(var[c] + 1e-6f);
        s_inv[tid]  = iv;
        s_bias[tid] = beta[c] - mean[c] * iv;
    }
    for (int i = tid; i < HEADS * 72; i += 256)
        kvs[i] = g_kv[(size_t)b * HEADS * 72 + i];
    __syncthreads();

    wmma::fragment<wmma::accumulator, 16, 16, 16, float> acc[2][4];
    #pragma unroll
    for (int mi = 0; mi < 2; mi++)
        #pragma unroll
        for (int pi = 0; pi < 4; pi++)
            wmma::fill_fragment(acc[mi][pi], 0.0f);

    const int hh = tid >> 7;
    const int px = tid & 127;
    const int arow  = tid >> 1;
    const int ahalf = (tid & 1) * 8;
    const __nv_bfloat16* wphiB = g_wphi + (size_t)(m0 + arow) * KDIM + ahalf;
    const __nv_bfloat16* wploB = g_wplo + (size_t)(m0 + arow) * KDIM + ahalf;

    for (int k0 = 0; k0 < KDIM; k0 += 16) {
        // A slab: pure uint4 copies of pre-converted weights
        *(uint4*)&sAhi[arow][ahalf] = *(const uint4*)(wphiB + k0);
        *(uint4*)&sAlo[arow][ahalf] = *(const uint4*)(wploB + k0);
        // B slab: att rows for heads (k0>>3)+hh
        {
            int h = (k0 >> 3) + hh;
            const float* qb = ms_ch(b, h * 24);
            const float* kvp = &kvs[h * 72];
            float q[8];
            #pragma unroll
            for (int d = 0; d < 8; d++)
                q[d] = fmaxf(qb[(size_t)d * HW_ + p0 + px], 0.f);
            float den = 0.f;
            #pragma unroll
            for (int d = 0; d < 8; d++) den = fmaf(q[d], kvp[d * 9 + 8], den);
            float r = 1.f / (den + 1e-15f);
            #pragma unroll
            for (int e = 0; e < 8; e++) {
                float s = 0.f;
                #pragma unroll
                for (int d = 0; d < 8; d++) s = fmaf(q[d], kvp[d * 9 + e], s);
                __nv_bfloat16 hi, lo;
                bsplit1(s * r, hi, lo);
                sBhi[hh * 8 + e][px] = hi;
                sBlo[hh * 8 + e][px] = lo;
            }
        }
        __syncthreads();

        wmma::fragment<wmma::matrix_a, 16, 16, 16, __nv_bfloat16, wmma::row_major> ahi[2], alo[2];
        #pragma unroll
        for (int mi = 0; mi < 2; mi++) {
            wmma::load_matrix_sync(ahi[mi], &sAhi[wy * 32 + mi * 16][0], 24);
            wmma::load_matrix_sync(alo[mi], &sAlo[wy * 32 + mi * 16][0], 24);
        }
        #pragma unroll
        for (int pi = 0; pi < 4; pi++) {
            wmma::fragment<wmma::matrix_b, 16, 16, 16, __nv_bfloat16, wmma::row_major> bhi, blo;
            wmma::load_matrix_sync(bhi, &sBhi[0][wx * 64 + pi * 16], 136);
            wmma::load_matrix_sync(blo, &sBlo[0][wx * 64 + pi * 16], 136);
            #pragma unroll
            for (int mi = 0; mi < 2; mi++) {
                wmma::mma_sync(acc[mi][pi], ahi[mi], bhi, acc[mi][pi]);
                wmma::mma_sync(acc[mi][pi], ahi[mi], blo, acc[mi][pi]);
                wmma::mma_sync(acc[mi][pi], alo[mi], bhi, acc[mi][pi]);
            }
        }
        __syncthreads();
    }

    // epilogue: stage, BN + residual, write
    const size_t cb = (size_t)b * 256 * HW_;
    #pragma unroll
    for (int mi = 0; mi < 2; mi++)
        #pragma unroll
        for (int pi = 0; pi < 4; pi++) {
            wmma::store_matrix_sync(&stage[wid][0], acc[mi][pi], 16, wmma::mem_row_major);
            __syncwarp();
            const int mloc0 = wy * 32 + mi * 16;
            const int pcol0 = p0 + wx * 64 + pi * 16;
            int idx = lane * 8;
            int r = idx >> 4;
            int c = idx & 15;
            int mloc = mloc0 + r;
            size_t go = cb + (size_t)(m0 + mloc) * HW_ + pcol0 + c;
            float iv = s_inv[mloc], bb = s_bias[mloc];
            float4 x0 = *(const float4*)(xres + go);
            float4 x1 = *(const float4*)(xres + go + 4);
            float* sp = &stage[wid][idx];
            float4 v0 = make_float4(
                fmaf(sp[0], iv, bb) + x0.x, fmaf(sp[1], iv, bb) + x0.y,
                fmaf(sp[2], iv, bb) + x0.z, fmaf(sp[3], iv, bb) + x0.w);
            float4 v1 = make_float4(
                fmaf(sp[4], iv, bb) + x1.x, fmaf(sp[5], iv, bb) + x1.y,
                fmaf(sp[6], iv, bb) + x1.z, fmaf(sp[7], iv, bb) + x1.w);
            *(float4*)(Cm + go)     = v0;
            *(float4*)(Cm + go + 4) = v1;
            __syncwarp();
        }
}

// ---------------- dwpw v2: warp-per-channel, weights in regs (R14) ----------
__global__ __launch_bounds__(256, 3) void dwpw_kernel(
    const float* __restrict__ w_dw, const float* __restrict__ w_pw)
{
    int blk = blockIdx.x;
    int tyi = blk & 7;
    int g   = (blk >> 3) % GRP;
    int b   = blk / (8 * GRP);
    int y0  = tyi * 8;

    __shared__ float s_in[8][12][68];
    __shared__ float s_dw[8][8 * 68];
    __shared__ float s_wpw[64];

    const int tid = threadIdx.x;
    if (tid < 64) s_wpw[tid] = w_pw[g * 64 + tid];

    const float* inb = g_qkv + ((size_t)(b * OC3 + g * 8)) * HW_;
    for (int idx = tid; idx < 8 * 12 * 68; idx += 256) {
        int i   = idx / (12 * 68);
        int rem = idx - i * (12 * 68);
        int r   = rem / 68;
        int cx  = rem - r * 68;
        int y   = y0 + r - 2;
        int xx  = cx - 2;
        float v = 0.f;
        if ((unsigned)y < 64u && (unsigned)xx < 64u)
            v = inb[(size_t)i * HW_ + y * W_ + xx];
        s_in[i][r][cx] = v;
    }

    const int ch = tid >> 5;
    const int lane = tid & 31;
    float w[25];
    {
        const float* wp = w_dw + g * 200 + ch * 25;
        #pragma unroll
        for (int t = 0; t < 25; t++) w[t] = wp[t];
    }
    __syncthreads();

    const int r = lane >> 2;
    const int cg = lane & 3;
    #pragma unroll
    for (int half = 0; half < 2; half++) {
        const int x0 = (cg + half * 4) * 8;
        float acc[8];
        #pragma unroll
        for (int j = 0; j < 8; j++) acc[j] = 0.f;
        #pragma unroll
        for (int dy = 0; dy < 5; dy++) {
            float4 v0 = *(const float4*)&s_in[ch][r + dy][x0];
            float4 v1 = *(const float4*)&s_in[ch][r + dy][x0 + 4];
            float4 v2 = *(const float4*)&s_in[ch][r + dy][x0 + 8];
            float v[12] = {v0.x, v0.y, v0.z, v0.w, v1.x, v1.y, v1.z, v1.w,
                           v2.x, v2.y, v2.z, v2.w};
            #pragma unroll
            for (int j = 0; j < 8; j++)
                #pragma unroll
                for (int dx = 0; dx < 5; dx++)
                    acc[j] = fmaf(v[j + dx], w[dy * 5 + dx], acc[j]);
        }
        #pragma unroll
        for (int j = 0; j < 4; j++) {
            *(float2*)&s_dw[ch][r * 68 + x0 + j * 2] =
                make_float2(acc[j * 2], acc[j * 2 + 1]);
        }
    }
    __syncthreads();

    #pragma unroll
    for (int pp = 0; pp < 2; pp++) {
        int px = tid + pp * 256;
        int yl = px >> 6;
        int x  = px & 63;
        float dwv[8];
        #pragma unroll
        for (int i = 0; i < 8; i++) dwv[i] = s_dw[i][yl * 68 + x];
        size_t obase = ((size_t)(b * OC3 + g * 8)) * HW_ + (size_t)(y0 + yl) * W_ + x;
        #pragma unroll
        for (int o = 0; o < 8; o++) {
            float s = 0.f;
            #pragma unroll
            for (int i = 0; i < 8; i++) s = fmaf(s_wpw[o * 8 + i], dwv[i], s);
            g_agg[obase + (size_t)o * HW_] = s;
        }
    }
}

// ---------------- kv = sum_n relu(k)[d] * [v,1][e]  per (b,head) ------------
__global__ __launch_bounds__(256) void kv_kernel()
{
    int blk = blockIdx.x;
    int b = blk >> 6;
    int h = blk & 63;
    const float* kb = ms_ch(b, h * 24 + 8);

    float acc[8][9];
    #pragma unroll
    for (int d = 0; d < 8; d++)
        #pragma unroll
        for (int e = 0; e < 9; e++) acc[d][e] = 0.f;

    int tid = threadIdx.x;
    for (int p = tid; p < HW_; p += 256) {
        float kk[8], vv[8];
        #pragma unroll
        for (int d = 0; d < 8; d++) kk[d] = fmaxf(kb[(size_t)d * HW_ + p], 0.f);
        #pragma unroll
        for (int d = 0; d < 8; d++) vv[d] = kb[(size_t)(8 + d) * HW_ + p];
        #pragma unroll
        for (int d = 0; d < 8; d++) {
            #pragma unroll
            for (int e = 0; e < 8; e++) acc[d][e] = fmaf(kk[d], vv[e], acc[d][e]);
            acc[d][8] += kk[d];
        }
    }

    #pragma unroll
    for (int d = 0; d < 8; d++)
        #pragma unroll
        for (int e = 0; e < 9; e++)
            #pragma unroll
            for (int off = 16; off > 0; off >>= 1)
                acc[d][e] += __shfl_down_sync(0xffffffffu, acc[d][e], off);

    __shared__ float red[8][72];
    int warp = tid >> 5, lane = tid & 31;
    if (lane == 0) {
        #pragma unroll
        for (int d = 0; d < 8; d++)
            #pragma unroll
            for (int e = 0; e < 9; e++) red[warp][d * 9 + e] = acc[d][e];
    }
    __syncthreads();
    if (tid < 72) {
        float s = 0.f;
        #pragma unroll
        for (int w = 0; w < 8; w++) s += red[w][tid];
        g_kv[(size_t)blk * 72 + tid] = s;
    }
}

// ---------------------------------------------------------------------------
extern "C" void kernel_launch(void* const* d_in, const int* in_sizes, int n_in,
                              void* d_out, int out_size)
{
    const float* x      = (const float*)d_in[0];
    const float* w_qkv  = (const float*)d_in[1];
    const float* w_dw   = (const float*)d_in[2];
    const float* w_pw   = (const float*)d_in[3];
    const float* w_proj = (const float*)d_in[4];
    const float* gamma  = (const float*)d_in[5];
    const float* beta   = (const float*)d_in[6];
    const float* mean   = (const float*)d_in[7];
    const float* var    = (const float*)d_in[8];
    float* out = (float*)d_out;

    __nv_bfloat16 *p_wqhi, *p_wqlo, *p_wphi, *p_wplo;
    cudaGetSymbolAddress((void**)&p_wqhi, g_wqhi);
    cudaGetSymbolAddress((void**)&p_wqlo, g_wqlo);
    cudaGetSymbolAddress((void**)&p_wphi, g_wphi);
    cudaGetSymbolAddress((void**)&p_wplo, g_wplo);
    float* p_qkv;
    cudaGetSymbolAddress((void**)&p_qkv, g_qkv);

    // 0) pre-convert weights to bf16 hi/lo (tiny)
    cvt_kernel<<<(OC3 * C_ / 4 + 255) / 256, 256>>>(w_qkv, p_wqhi, p_wqlo, OC3 * C_ / 4);
    cvt_kernel<<<(C_ * 512 / 4 + 255) / 256, 256>>>(w_proj, p_wphi, p_wplo, C_ * 512 / 4);

    // 1) qkv = w_qkv @ x  (wmma bf16-split, A from pre-converted)
    qkv_wmma_kernel<<<dim3(256, 6), 256>>>(x, p_qkv);
    // 2) depthwise 5x5 + grouped pointwise -> agg
    dwpw_kernel<<<6144, 256>>>(w_dw, w_pw);
    // 3) per-head kv reduction
    kv_kernel<<<512, 256>>>();
    // 4) proj GEMM (wmma, A from pre-converted) + fused att + BN + residual
    proj_wmma_kernel<<<dim3(256, 2), 256>>>(out, x, gamma, beta, mean, var);
}

// round 17
// speedup vs baseline: 1.1604x; 1.1604x over previous
#include <cuda_runtime.h>
#include <cuda_bf16.h>
#include <mma.h>
#include <cstdint>

using namespace nvcuda;

#define B_    8
#define C_    256
#define HW_   4096
#define W_    64
#define OC3   768
#define GRP   96
#define HEADS 64

// ------------------------- scratch (static device memory) -------------------
__device__ float g_qkv[(size_t)B_ * OC3 * HW_];
__device__ float g_agg[(size_t)B_ * OC3 * HW_];
__device__ float g_att[(size_t)B_ * 512 * HW_];
__device__ float g_kv [(size_t)B_ * HEADS * 72];

__device__ __forceinline__ const float* ms_ch(int b, int c) {
    return (c < OC3) ? (g_qkv + ((size_t)(b * OC3 + c)) * HW_)
                     : (g_agg + ((size_t)(b * OC3 + (c - OC3))) * HW_);
}

__device__ __forceinline__ void bsplit2(float x, float y,
                                        __nv_bfloat162& hi, __nv_bfloat162& lo)
{
    __nv_bfloat16 hx = __float2bfloat16(x);
    __nv_bfloat16 hy = __float2bfloat16(y);
    __nv_bfloat16 lx = __float2bfloat16(x - __bfloat162float(hx));
    __nv_bfloat16 ly = __float2bfloat16(y - __bfloat162float(hy));
    hi = __halves2bfloat162(hx, hy);
    lo = __halves2bfloat162(lx, ly);
}

// -------- generic wmma bf16-split GEMM body (A [M,K] f32, B [B_,K,HW] f32) --
// CTA 128(m) x 128(p); 8 warps each 32(m) x 64(p). Conversion in-kernel.
template <int KDIM>
__device__ __forceinline__ void gemm_body(
    const float* __restrict__ A, const float* __restrict__ Bbase,
    int m0, int tid,
    __nv_bfloat16 (*sAhi)[24], __nv_bfloat16 (*sAlo)[24],
    __nv_bfloat16 (*sBhi)[136], __nv_bfloat16 (*sBlo)[136],
    wmma::fragment<wmma::accumulator, 16, 16, 16, float> (*acc)[4])
{
    const int wid = tid >> 5;
    const int wy = wid >> 1;
    const int wx = wid & 1;

    for (int k0 = 0; k0 < KDIM; k0 += 16) {
        #pragma unroll
        for (int it = 0; it < 2; it++) {
            int lin = tid + it * 256;
            int m  = lin >> 2;
            int kq = (lin & 3) * 4;
            float4 v = *(const float4*)(A + (size_t)(m0 + m) * KDIM + k0 + kq);
            __nv_bfloat162 h0, l0, h1, l1;
            bsplit2(v.x, v.y, h0, l0);
            bsplit2(v.z, v.w, h1, l1);
            *(__nv_bfloat162*)&sAhi[m][kq]     = h0;
            *(__nv_bfloat162*)&sAhi[m][kq + 2] = h1;
            *(__nv_bfloat162*)&sAlo[m][kq]     = l0;
            *(__nv_bfloat162*)&sAlo[m][kq + 2] = l1;
        }
        #pragma unroll
        for (int it = 0; it < 2; it++) {
            int lin = tid + it * 256;
            int kr = lin >> 5;
            int pq = (lin & 31) * 4;
            float4 v = *(const float4*)(Bbase + (size_t)(k0 + kr) * HW_ + pq);
            __nv_bfloat162 h0, l0, h1, l1;
            bsplit2(v.x, v.y, h0, l0);
            bsplit2(v.z, v.w, h1, l1);
            *(__nv_bfloat162*)&sBhi[kr][pq]     = h0;
            *(__nv_bfloat162*)&sBhi[kr][pq + 2] = h1;
            *(__nv_bfloat162*)&sBlo[kr][pq]     = l0;
            *(__nv_bfloat162*)&sBlo[kr][pq + 2] = l1;
        }
        __syncthreads();

        wmma::fragment<wmma::matrix_a, 16, 16, 16, __nv_bfloat16, wmma::row_major> ahi[2], alo[2];
        #pragma unroll
        for (int mi = 0; mi < 2; mi++) {
            wmma::load_matrix_sync(ahi[mi], &sAhi[wy * 32 + mi * 16][0], 24);
            wmma::load_matrix_sync(alo[mi], &sAlo[wy * 32 + mi * 16][0], 24);
        }
        #pragma unroll
        for (int pi = 0; pi < 4; pi++) {
            wmma::fragment<wmma::matrix_b, 16, 16, 16, __nv_bfloat16, wmma::row_major> bhi, blo;
            wmma::load_matrix_sync(bhi, &sBhi[0][wx * 64 + pi * 16], 136);
            wmma::load_matrix_sync(blo, &sBlo[0][wx * 64 + pi * 16], 136);
            #pragma unroll
            for (int mi = 0; mi < 2; mi++) {
                wmma::mma_sync(acc[mi][pi], ahi[mi], bhi, acc[mi][pi]);
                wmma::mma_sync(acc[mi][pi], ahi[mi], blo, acc[mi][pi]);
                wmma::mma_sync(acc[mi][pi], alo[mi], bhi, acc[mi][pi]);
            }
        }
        __syncthreads();
    }
}

// ------------------- qkv GEMM via wmma bf16-split (R11/R14) -----------------
__global__ __launch_bounds__(256, 2) void qkv_wmma_kernel(
    const float* __restrict__ A, const float* __restrict__ Bm,
    float* __restrict__ Cm)
{
    __shared__ __nv_bfloat16 sAhi[128][24];
    __shared__ __nv_bfloat16 sAlo[128][24];
    __shared__ __nv_bfloat16 sBhi[16][136];
    __shared__ __nv_bfloat16 sBlo[16][136];

    const int m0 = blockIdx.y * 128;
    const int n0 = blockIdx.x * 128;
    const int b  = n0 >> 12;
    const int p0 = n0 & 4095;
    const int tid = threadIdx.x;
    const int wid = tid >> 5;
    const int wy = wid >> 1;
    const int wx = wid & 1;

    wmma::fragment<wmma::accumulator, 16, 16, 16, float> acc[2][4];
    #pragma unroll
    for (int mi = 0; mi < 2; mi++)
        #pragma unroll
        for (int pi = 0; pi < 4; pi++)
            wmma::fill_fragment(acc[mi][pi], 0.0f);

    gemm_body<256>(A, Bm + (size_t)b * 256 * HW_ + p0, m0, tid,
                   sAhi, sAlo, sBhi, sBlo, acc);

    const size_t cb = (size_t)b * OC3 * HW_;
    #pragma unroll
    for (int mi = 0; mi < 2; mi++)
        #pragma unroll
        for (int pi = 0; pi < 4; pi++) {
            float* cp = Cm + cb + (size_t)(m0 + wy * 32 + mi * 16) * HW_
                        + p0 + wx * 64 + pi * 16;
            wmma::store_matrix_sync(cp, acc[mi][pi], HW_, wmma::mem_row_major);
        }
}

// ---------- proj GEMM via wmma bf16-split from g_att, BN + residual ---------
__global__ __launch_bounds__(256, 2) void proj_wmma_kernel(
    const float* __restrict__ A, const float* __restrict__ Bm,
    float* __restrict__ Cm, const float* __restrict__ xres,
    const float* __restrict__ gamma, const float* __restrict__ beta,
    const float* __restrict__ mean, const float* __restrict__ var)
{
    __shared__ __nv_bfloat16 sAhi[128][24];
    __shared__ __nv_bfloat16 sAlo[128][24];
    __shared__ __nv_bfloat16 sBhi[16][136];
    __shared__ __nv_bfloat16 sBlo[16][136];
    __shared__ float s_inv[128];
    __shared__ float s_bias[128];
    __shared__ float stage[8][256];

    const int m0 = blockIdx.y * 128;
    const int n0 = blockIdx.x * 128;
    const int b  = n0 >> 12;
    const int p0 = n0 & 4095;
    const int tid = threadIdx.x;
    const int wid = tid >> 5;
    const int lane = tid & 31;
    const int wy = wid >> 1;
    const int wx = wid & 1;

    if (tid < 128) {
        int c = m0 + tid;
        float iv = gamma[c] * rsqrtf(var[c] + 1e-6f);
        s_inv[tid]  = iv;
        s_bias[tid] = beta[c] - mean[c] * iv;
    }
    __syncthreads();

    wmma::fragment<wmma::accumulator, 16, 16, 16, float> acc[2][4];
    #pragma unroll
    for (int mi = 0; mi < 2; mi++)
        #pragma unroll
        for (int pi = 0; pi < 4; pi++)
            wmma::fill_fragment(acc[mi][pi], 0.0f);

    gemm_body<512>(A, Bm + (size_t)b * 512 * HW_ + p0, m0, tid,
                   sAhi, sAlo, sBhi, sBlo, acc);

    // epilogue: stage, BN + residual, write
    const size_t cb = (size_t)b * 256 * HW_;
    #pragma unroll
    for (int mi = 0; mi < 2; mi++)
        #pragma unroll
        for (int pi = 0; pi < 4; pi++) {
            wmma::store_matrix_sync(&stage[wid][0], acc[mi][pi], 16, wmma::mem_row_major);
            __syncwarp();
            const int mloc0 = wy * 32 + mi * 16;
            const int pcol0 = p0 + wx * 64 + pi * 16;
            int idx = lane * 8;
            int r = idx >> 4;
            int c = idx & 15;
            int mloc = mloc0 + r;
            size_t go = cb + (size_t)(m0 + mloc) * HW_ + pcol0 + c;
            float iv = s_inv[mloc], bb = s_bias[mloc];
            float4 x0 = *(const float4*)(xres + go);
            float4 x1 = *(const float4*)(xres + go + 4);
            float* sp = &stage[wid][idx];
            float4 v0 = make_float4(
                fmaf(sp[0], iv, bb) + x0.x, fmaf(sp[1], iv, bb) + x0.y,
                fmaf(sp[2], iv, bb) + x0.z, fmaf(sp[3], iv, bb) + x0.w);
            float4 v1 = make_float4(
                fmaf(sp[4], iv, bb) + x1.x, fmaf(sp[5], iv, bb) + x1.y,
                fmaf(sp[6], iv, bb) + x1.z, fmaf(sp[7], iv, bb) + x1.w);
            *(float4*)(Cm + go)     = v0;
            *(float4*)(Cm + go + 4) = v1;
            __syncwarp();
        }
}

// ---------------- att = (q @ kv)[:8] / ((q @ kv)[8] + eps)  (R5) ------------
__global__ __launch_bounds__(256) void att_kernel()
{
    int blk = blockIdx.x;
    int pt = blk & 15;
    int h  = (blk >> 4) & 63;
    int b  = blk >> 10;

    __shared__ float kv[72];
    int tid = threadIdx.x;
    if (tid < 72) kv[tid] = g_kv[(size_t)(b * HEADS + h) * 72 + tid];
    __syncthreads();

    int p = pt * 256 + tid;
    const float* qp = ms_ch(b, h * 24);
    float q[8];
    #pragma unroll
    for (int d = 0; d < 8; d++) q[d] = fmaxf(qp[(size_t)d * HW_ + p], 0.f);

    float num[9];
    #pragma unroll
    for (int e = 0; e < 9; e++) {
        float s = 0.f;
        #pragma unroll
        for (int d = 0; d < 8; d++) s = fmaf(q[d], kv[d * 9 + e], s);
        num[e] = s;
    }
    float r = 1.f / (num[8] + 1e-15f);
    float* op = g_att + ((size_t)(b * 512 + h * 8)) * HW_ + p;
    #pragma unroll
    for (int e = 0; e < 8; e++) op[(size_t)e * HW_] = num[e] * r;
}

// ---------------- dwpw v2: warp-per-channel, weights in regs (R14) ----------
__global__ __launch_bounds__(256, 3) void dwpw_kernel(
    const float* __restrict__ w_dw, const float* __restrict__ w_pw)
{
    int blk = blockIdx.x;
    int tyi = blk & 7;
    int g   = (blk >> 3) % GRP;
    int b   = blk / (8 * GRP);
    int y0  = tyi * 8;

    __shared__ float s_in[8][12][68];
    __shared__ float s_dw[8][8 * 68];
    __shared__ float s_wpw[64];

    const int tid = threadIdx.x;
    if (tid < 64) s_wpw[tid] = w_pw[g * 64 + tid];

    const float* inb = g_qkv + ((size_t)(b * OC3 + g * 8)) * HW_;
    for (int idx = tid; idx < 8 * 12 * 68; idx += 256) {
        int i   = idx / (12 * 68);
        int rem = idx - i * (12 * 68);
        int r   = rem / 68;
        int cx  = rem - r * 68;
        int y   = y0 + r - 2;
        int xx  = cx - 2;
        float v = 0.f;
        if ((unsigned)y < 64u && (unsigned)xx < 64u)
            v = inb[(size_t)i * HW_ + y * W_ + xx];
        s_in[i][r][cx] = v;
    }

    const int ch = tid >> 5;
    const int lane = tid & 31;
    float w[25];
    {
        const float* wp = w_dw + g * 200 + ch * 25;
        #pragma unroll
        for (int t = 0; t < 25; t++) w[t] = wp[t];
    }
    __syncthreads();

    const int r = lane >> 2;
    const int cg = lane & 3;
    #pragma unroll
    for (int half = 0; half < 2; half++) {
        const int x0 = (cg + half * 4) * 8;
        float acc[8];
        #pragma unroll
        for (int j = 0; j < 8; j++) acc[j] = 0.f;
        #pragma unroll
        for (int dy = 0; dy < 5; dy++) {
            float4 v0 = *(const float4*)&s_in[ch][r + dy][x0];
            float4 v1 = *(const float4*)&s_in[ch][r + dy][x0 + 4];
            float4 v2 = *(const float4*)&s_in[ch][r + dy][x0 + 8];
            float v[12] = {v0.x, v0.y, v0.z, v0.w, v1.x, v1.y, v1.z, v1.w,
                           v2.x, v2.y, v2.z, v2.w};
            #pragma unroll
            for (int j = 0; j < 8; j++)
                #pragma unroll
                for (int dx = 0; dx < 5; dx++)
                    acc[j] = fmaf(v[j + dx], w[dy * 5 + dx], acc[j]);
        }
        #pragma unroll
        for (int j = 0; j < 4; j++) {
            *(float2*)&s_dw[ch][r * 68 + x0 + j * 2] =
                make_float2(acc[j * 2], acc[j * 2 + 1]);
        }
    }
    __syncthreads();

    #pragma unroll
    for (int pp = 0; pp < 2; pp++) {
        int px = tid + pp * 256;
        int yl = px >> 6;
        int x  = px & 63;
        float dwv[8];
        #pragma unroll
        for (int i = 0; i < 8; i++) dwv[i] = s_dw[i][yl * 68 + x];
        size_t obase = ((size_t)(b * OC3 + g * 8)) * HW_ + (size_t)(y0 + yl) * W_ + x;
        #pragma unroll
        for (int o = 0; o < 8; o++) {
            float s = 0.f;
            #pragma unroll
            for (int i = 0; i < 8; i++) s = fmaf(s_wpw[o * 8 + i], dwv[i], s);
            g_agg[obase + (size_t)o * HW_] = s;
        }
    }
}

// ---------------- kv = sum_n relu(k)[d] * [v,1][e]  per (b,head) ------------
__global__ __launch_bounds__(256) void kv_kernel()
{
    int blk = blockIdx.x;
    int b = blk >> 6;
    int h = blk & 63;
    const float* kb = ms_ch(b, h * 24 + 8);

    float acc[8][9];
    #pragma unroll
    for (int d = 0; d < 8; d++)
        #pragma unroll
        for (int e = 0; e < 9; e++) acc[d][e] = 0.f;

    int tid = threadIdx.x;
    for (int p = tid; p < HW_; p += 256) {
        float kk[8], vv[8];
        #pragma unroll
        for (int d = 0; d < 8; d++) kk[d] = fmaxf(kb[(size_t)d * HW_ + p], 0.f);
        #pragma unroll
        for (int d = 0; d < 8; d++) vv[d] = kb[(size_t)(8 + d) * HW_ + p];
        #pragma unroll
        for (int d = 0; d < 8; d++) {
            #pragma unroll
            for (int e = 0; e < 8; e++) acc[d][e] = fmaf(kk[d], vv[e], acc[d][e]);
            acc[d][8] += kk[d];
        }
    }

    #pragma unroll
    for (int d = 0; d < 8; d++)
        #pragma unroll
        for (int e = 0; e < 9; e++)
            #pragma unroll
            for (int off = 16; off > 0; off >>= 1)
                acc[d][e] += __shfl_down_sync(0xffffffffu, acc[d][e], off);

    __shared__ float red[8][72];
    int warp = tid >> 5, lane = tid & 31;
    if (lane == 0) {
        #pragma unroll
        for (int d = 0; d < 8; d++)
            #pragma unroll
            for (int e = 0; e < 9; e++) red[warp][d * 9 + e] = acc[d][e];
    }
    __syncthreads();
    if (tid < 72) {
        float s = 0.f;
        #pragma unroll
        for (int w = 0; w < 8; w++) s += red[w][tid];
        g_kv[(size_t)blk * 72 + tid] = s;
    }
}

// ---------------------------------------------------------------------------
extern "C" void kernel_launch(void* const* d_in, const int* in_sizes, int n_in,
                              void* d_out, int out_size)
{
    const float* x      = (const float*)d_in[0];
    const float* w_qkv  = (const float*)d_in[1];
    const float* w_dw   = (const float*)d_in[2];
    const float* w_pw   = (const float*)d_in[3];
    const float* w_proj = (const float*)d_in[4];
    const float* gamma  = (const float*)d_in[5];
    const float* beta   = (const float*)d_in[6];
    const float* mean   = (const float*)d_in[7];
    const float* var    = (const float*)d_in[8];
    float* out = (float*)d_out;

    float *p_qkv, *p_att;
    cudaGetSymbolAddress((void**)&p_qkv, g_qkv);
    cudaGetSymbolAddress((void**)&p_att, g_att);

    // 1) qkv = w_qkv @ x  (wmma bf16-split, in-kernel conversion)
    qkv_wmma_kernel<<<dim3(256, 6), 256>>>(w_qkv, x, p_qkv);
    // 2) depthwise 5x5 + grouped pointwise -> agg
    dwpw_kernel<<<6144, 256>>>(w_dw, w_pw);
    // 3) per-head kv reduction
    kv_kernel<<<512, 256>>>();
    // 4) attention output -> g_att
    att_kernel<<<8192, 256>>>();
    // 5) proj GEMM (wmma bf16-split from g_att) + BN + residual
    proj_wmma_kernel<<<dim3(256, 2), 256>>>(w_proj, p_att, out, x,
                                            gamma, beta, mean, var);
}